// round 4
// baseline (speedup 1.0000x reference)
#include <cuda_runtime.h>

#define BDIM 64
#define TDIM 24
#define NNODE 300
#define FDIM 16
#define DDIM 64
#define BT (BDIM*TDIM)          // 1536
#define ND (NNODE*DDIM)         // 19200
#define NC1 128
#define NC2 128
#define MLPIN (ND + NC2)        // 19328
#define H1DIM 512
#define H2DIM 256
#define OUTD 3600               // N*H = 300*12
#define MLP1_STEPS (MLPIN/16)   // 1208
#define MLP1_KS 16
#define MLP1_SPS 76             // ceil(1208/16)
#define CONV1_KS 2              // split-K for conv1 GEMM
#define GSTRIDE ((size_t)BT*384)
#define NCHUNK 60               // adj smem tile width in gcn2 phase 3

// ---------------- device scratch (no allocations allowed) ----------------
__device__ float g_h1[(size_t)BT*ND];
__device__ float g_h2[(size_t)BT*ND];
__device__ float g_wp1[(size_t)ND*384];
__device__ float g_wp2[(size_t)NC1*384];
__device__ float g_gbuf[(size_t)CONV1_KS*BT*384];
__device__ float g_y1[(size_t)BT*NC1];
__device__ float g_y2[(size_t)BT*NC2];
__device__ float g_comb[(size_t)BDIM*MLPIN];
__device__ float g_p1[(size_t)MLP1_KS*64*H1DIM];
__device__ float g_z1[BDIM*H1DIM];
__device__ float g_z2[BDIM*H2DIM];

// ---------------- pack conv weight: wp[i*384 + c*3+k] = w[c,i,k] ----------
__global__ void pack_conv_w(const float* __restrict__ w, float* __restrict__ wp, int cin) {
    int idx = blockIdx.x * 256 + threadIdx.x;
    int tot = cin * 384;
    if (idx >= tot) return;
    int i = idx / 384, j = idx % 384;
    int c = j / 3, k = j % 3;
    wp[idx] = w[((size_t)c * cin + i) * 3 + k];
}

// ---------------- GCN layer 1: h1 = relu((A@x)@W1 + b1), per (b,t) --------
__global__ void __launch_bounds__(256) gcn1_kernel(const float* __restrict__ x,
                                                   const float* __restrict__ adj,
                                                   const float* __restrict__ w1,
                                                   const float* __restrict__ b1) {
    __shared__ float4 xs[NNODE * 4];    // x tile, [n][fquad]
    __shared__ float4 axs[NNODE * 4];   // A@x,   [m][fquad]
    __shared__ float  w1s[FDIM * DDIM];
    __shared__ float  b1s[DDIM];
    int bt = blockIdx.x;
    int tid = threadIdx.x;

    const float4* xin = (const float4*)(x + (size_t)bt * NNODE * FDIM);
    for (int i = tid; i < NNODE * 4; i += 256) xs[i] = xin[i];
    for (int i = tid; i < FDIM * DDIM; i += 256) w1s[i] = w1[i];
    if (tid < DDIM) b1s[tid] = b1[tid];
    __syncthreads();

    // Phase A: AX[m][f] = sum_n adj[m][n] * x[n][f]
    // one thread per m row: adj row read exactly once (no fq redundancy)
    for (int rep = 0; rep < 2; ++rep) {
        int m = rep * 256 + tid;
        if (m < NNODE) {
            float4 acc[4];
            #pragma unroll
            for (int q = 0; q < 4; ++q) acc[q] = make_float4(0.f, 0.f, 0.f, 0.f);
            const float4* arow4 = (const float4*)(adj + (size_t)m * NNODE);
            for (int n4 = 0; n4 < NNODE / 4; ++n4) {
                float4 av = arow4[n4];
                float a[4] = {av.x, av.y, av.z, av.w};
                #pragma unroll
                for (int j = 0; j < 4; ++j) {
                    #pragma unroll
                    for (int q = 0; q < 4; ++q) {
                        float4 xv = xs[(n4 * 4 + j) * 4 + q];
                        acc[q].x += a[j] * xv.x; acc[q].y += a[j] * xv.y;
                        acc[q].z += a[j] * xv.z; acc[q].w += a[j] * xv.w;
                    }
                }
            }
            #pragma unroll
            for (int q = 0; q < 4; ++q) axs[m * 4 + q] = acc[q];
        }
    }
    __syncthreads();

    // Phase B: h1[m][d] = relu(sum_f AX[m][f]*W1[f][d] + b1[d])
    int d = tid & 63;
    int mr2 = tid >> 6;                 // 0..3
    float* out = g_h1 + (size_t)bt * ND;
    const float* axf = (const float*)axs;
    for (int pass = 0; pass < 75; ++pass) {
        int m = pass * 4 + mr2;
        float acc = b1s[d];
        #pragma unroll
        for (int f = 0; f < 16; ++f)
            acc += axf[m * 16 + f] * w1s[f * 64 + d];
        out[(size_t)m * 64 + d] = fmaxf(acc, 0.f);
    }
}

// ------- GCN layer 2 fused: S2 = h1@W2 (smem), h2 = relu(A@S2 + b2) -------
extern __shared__ float g2_sm[];
__global__ void __launch_bounds__(256) gcn2_kernel(const float* __restrict__ adj,
                                                   const float* __restrict__ w2,
                                                   const float* __restrict__ b2) {
    float* h1s = g2_sm;                 // 19200 (reused as adj tile in phase 3)
    float* s2s = g2_sm + ND;            // 19200
    float* w2s = g2_sm + 2 * ND;        // 4096
    float* b2s = g2_sm + 2 * ND + 4096; // 64
    int bt = blockIdx.x, tid = threadIdx.x;

    const float4* hin = (const float4*)(g_h1 + (size_t)bt * ND);
    float4* h1s4 = (float4*)h1s;
    for (int i = tid; i < ND / 4; i += 256) h1s4[i] = hin[i];
    for (int i = tid; i < DDIM * DDIM; i += 256) w2s[i] = w2[i];
    if (tid < DDIM) b2s[tid] = b2[tid];
    __syncthreads();

    // Phase 2: s2s[m][d] = sum_e h1s[m][e]*w2[e][d]   (4m x 4d per thread)
    {
        int tc = tid & 15, tr = tid >> 4;
        int d0 = tc * 4;
        for (int pass = 0; pass < 5; ++pass) {
            int m0 = pass * 64 + tr * 4;
            int mi[4];
            #pragma unroll
            for (int i = 0; i < 4; ++i) mi[i] = (m0 + i < NNODE) ? (m0 + i) : (NNODE - 1);
            float acc[4][4] = {};
            #pragma unroll 4
            for (int e = 0; e < 64; ++e) {
                float4 bv = *(const float4*)&w2s[e * 64 + d0];
                #pragma unroll
                for (int i = 0; i < 4; ++i) {
                    float a = h1s[mi[i] * 64 + e];
                    acc[i][0] += a * bv.x; acc[i][1] += a * bv.y;
                    acc[i][2] += a * bv.z; acc[i][3] += a * bv.w;
                }
            }
            #pragma unroll
            for (int i = 0; i < 4; ++i)
                if (m0 + i < NNODE)
                    *(float4*)&s2s[(m0 + i) * 64 + d0] =
                        make_float4(acc[i][0], acc[i][1], acc[i][2], acc[i][3]);
        }
    }
    __syncthreads();

    // Phase 3: h2[m][d] = relu(sum_n adj[m][n]*s2s[n][d] + b2[d])  (4m x 8d)
    // adj staged through smem (h1s region, dead after phase 2) in 300xNCHUNK tiles
    {
        float* adjs = h1s;              // NNODE*NCHUNK = 18000 floats <= 19200
        int tc = tid & 7, tr = tid >> 3;
        int d0 = tc * 8;
        float* out = g_h2 + (size_t)bt * ND;
        for (int pass = 0; pass < 3; ++pass) {
            int m0 = pass * 128 + tr * 4;
            int mi[4];
            #pragma unroll
            for (int i = 0; i < 4; ++i) mi[i] = (m0 + i < NNODE) ? (m0 + i) : (NNODE - 1);
            float acc[4][8] = {};
            for (int chunk = 0; chunk < NNODE / NCHUNK; ++chunk) {
                int n0 = chunk * NCHUNK;
                __syncthreads();        // previous tile fully consumed
                for (int idx = tid; idx < NNODE * NCHUNK; idx += 256)
                    adjs[idx] = adj[(size_t)(idx / NCHUNK) * NNODE + n0 + (idx % NCHUNK)];
                __syncthreads();
                for (int nl4 = 0; nl4 < NCHUNK / 4; ++nl4) {
                    float a[16];
                    #pragma unroll
                    for (int i = 0; i < 4; ++i) {
                        float4 av = *(const float4*)&adjs[mi[i] * NCHUNK + nl4 * 4];
                        a[i * 4 + 0] = av.x; a[i * 4 + 1] = av.y;
                        a[i * 4 + 2] = av.z; a[i * 4 + 3] = av.w;
                    }
                    #pragma unroll
                    for (int j = 0; j < 4; ++j) {
                        int n = n0 + nl4 * 4 + j;
                        float4 s0 = *(const float4*)&s2s[n * 64 + d0];
                        float4 s1 = *(const float4*)&s2s[n * 64 + d0 + 4];
                        #pragma unroll
                        for (int i = 0; i < 4; ++i) {
                            float aa = a[i * 4 + j];
                            acc[i][0] += aa * s0.x; acc[i][1] += aa * s0.y;
                            acc[i][2] += aa * s0.z; acc[i][3] += aa * s0.w;
                            acc[i][4] += aa * s1.x; acc[i][5] += aa * s1.y;
                            acc[i][6] += aa * s1.z; acc[i][7] += aa * s1.w;
                        }
                    }
                }
            }
            #pragma unroll
            for (int i = 0; i < 4; ++i) {
                int m = m0 + i;
                if (m < NNODE) {
                    float4 r0, r1;
                    r0.x = fmaxf(acc[i][0] + b2s[d0 + 0], 0.f);
                    r0.y = fmaxf(acc[i][1] + b2s[d0 + 1], 0.f);
                    r0.z = fmaxf(acc[i][2] + b2s[d0 + 2], 0.f);
                    r0.w = fmaxf(acc[i][3] + b2s[d0 + 3], 0.f);
                    r1.x = fmaxf(acc[i][4] + b2s[d0 + 4], 0.f);
                    r1.y = fmaxf(acc[i][5] + b2s[d0 + 5], 0.f);
                    r1.z = fmaxf(acc[i][6] + b2s[d0 + 6], 0.f);
                    r1.w = fmaxf(acc[i][7] + b2s[d0 + 7], 0.f);
                    *(float4*)&out[(size_t)m * 64 + d0] = r0;
                    *(float4*)&out[(size_t)m * 64 + d0 + 4] = r1;
                }
            }
        }
    }
}

// ------- generic 64x64 SGEMM, BK=16, double-buffered, optional split-K ----
// grid = (Mtiles, Ntiles, Ksplits). C row-major ldc. K = ktotal_steps*16.
__global__ void __launch_bounds__(256) sgemm64(const float* __restrict__ A, int lda,
                                               const float* __restrict__ B, int ldb,
                                               float* __restrict__ C, int ldc,
                                               int ktotal_steps, int steps_per_split,
                                               size_t c_split_stride) {
    __shared__ float As[2][16][64];
    __shared__ float Bs[2][16][64];
    int tid = threadIdx.x;
    int r0 = blockIdx.x * 64, j0 = blockIdx.y * 64;
    int s0 = blockIdx.z * steps_per_split;
    int nst = ktotal_steps - s0;
    if (nst > steps_per_split) nst = steps_per_split;
    if (nst <= 0) return;
    C += (size_t)blockIdx.z * c_split_stride;

    int la_r = tid >> 2, la_k = (tid & 3) * 4;
    int lb_k = tid >> 4, lb_j = (tid & 15) * 4;
    const float* Ap = A + (size_t)(r0 + la_r) * lda + s0 * 16 + la_k;
    const float* Bp = B + ((size_t)s0 * 16 + lb_k) * ldb + j0 + lb_j;

    float4 a4 = *(const float4*)Ap;
    float4 b4 = *(const float4*)Bp;
    float acc[4][4] = {};
    int tc = tid & 15, tr = tid >> 4;
    int buf = 0;
    for (int s = 0; s < nst; ++s) {
        As[buf][la_k + 0][la_r] = a4.x;
        As[buf][la_k + 1][la_r] = a4.y;
        As[buf][la_k + 2][la_r] = a4.z;
        As[buf][la_k + 3][la_r] = a4.w;
        *(float4*)&Bs[buf][lb_k][lb_j] = b4;
        __syncthreads();
        if (s + 1 < nst) {
            a4 = *(const float4*)(Ap + (size_t)(s + 1) * 16);
            b4 = *(const float4*)(Bp + (size_t)(s + 1) * 16 * ldb);
        }
        #pragma unroll
        for (int kk = 0; kk < 16; ++kk) {
            float4 av = *(const float4*)&As[buf][kk][tr * 4];
            float4 bv = *(const float4*)&Bs[buf][kk][tc * 4];
            acc[0][0] += av.x * bv.x; acc[0][1] += av.x * bv.y; acc[0][2] += av.x * bv.z; acc[0][3] += av.x * bv.w;
            acc[1][0] += av.y * bv.x; acc[1][1] += av.y * bv.y; acc[1][2] += av.y * bv.z; acc[1][3] += av.y * bv.w;
            acc[2][0] += av.z * bv.x; acc[2][1] += av.z * bv.y; acc[2][2] += av.z * bv.z; acc[2][3] += av.z * bv.w;
            acc[3][0] += av.w * bv.x; acc[3][1] += av.w * bv.y; acc[3][2] += av.w * bv.z; acc[3][3] += av.w * bv.w;
        }
        buf ^= 1;
    }
    #pragma unroll
    for (int i = 0; i < 4; ++i) {
        *(float4*)&C[(size_t)(r0 + tr * 4 + i) * ldc + j0 + tc * 4] =
            make_float4(acc[i][0], acc[i][1], acc[i][2], acc[i][3]);
    }
}

// ------- temporal 3-tap combine over nsplit partial GEMM buffers ----------
// y[bt,c] = relu(sum_s (G[s][bt-1,3c] + G[s][bt,3c+1] + G[s][bt+1,3c+2]) + b[c])
__global__ void conv_combine(const float* __restrict__ G, const float* __restrict__ bias,
                             float* __restrict__ y, int nsplit) {
    int idx = blockIdx.x * 256 + threadIdx.x;
    if (idx >= BT * 128) return;
    int c = idx & 127;
    int bt = idx >> 7;
    int t = bt % TDIM;
    float v = bias[c];
    for (int s = 0; s < nsplit; ++s) {
        const float* Gs = G + (size_t)s * GSTRIDE;
        if (t > 0)        v += Gs[(size_t)(bt - 1) * 384 + c * 3 + 0];
        v += Gs[(size_t)bt * 384 + c * 3 + 1];
        if (t < TDIM - 1) v += Gs[(size_t)(bt + 1) * 384 + c * 3 + 2];
    }
    y[idx] = fmaxf(v, 0.f);
}

// ------- concat [last_spatial | mean_t(y2)]  (pool fused in) --------------
__global__ void gather_comb() {
    int idx = blockIdx.x * 256 + threadIdx.x;   // 64*19328
    if (idx >= BDIM * MLPIN) return;
    int b = idx / MLPIN, j = idx - b * MLPIN;
    if (j < ND) {
        g_comb[idx] = g_h2[((size_t)(b * TDIM + (TDIM - 1))) * ND + j];
    } else {
        int c = j - ND;
        float s = 0.f;
        #pragma unroll
        for (int t = 0; t < TDIM; ++t) s += g_y2[(size_t)(b * TDIM + t) * NC2 + c];
        g_comb[idx] = s * (1.f / TDIM);
    }
}

__global__ void mlp1_reduce(const float* __restrict__ b1) {
    int o = blockIdx.x * 256 + threadIdx.x;     // 64*512
    if (o >= BDIM * H1DIM) return;
    int j = o & (H1DIM - 1);
    float s = b1[j];
    #pragma unroll
    for (int ks = 0; ks < MLP1_KS; ++ks) s += g_p1[(size_t)ks * 64 * H1DIM + o];
    g_z1[o] = fmaxf(s, 0.f);
}

__global__ void __launch_bounds__(256) mlp2_kernel(const float* __restrict__ w,
                                                   const float* __restrict__ b) {
    __shared__ float zs[H1DIM];
    int bb = blockIdx.x, tid = threadIdx.x;
    zs[tid] = g_z1[bb * H1DIM + tid];
    zs[tid + 256] = g_z1[bb * H1DIM + tid + 256];
    __syncthreads();
    float acc = b[tid];
    #pragma unroll 8
    for (int k = 0; k < H1DIM; ++k) acc += zs[k] * w[(size_t)k * H2DIM + tid];
    g_z2[bb * H2DIM + tid] = fmaxf(acc, 0.f);
}

__global__ void __launch_bounds__(256) mlp3_kernel(const float* __restrict__ w,
                                                   const float* __restrict__ b,
                                                   float* __restrict__ out) {
    __shared__ float zs[H2DIM];
    int bb = blockIdx.x, tid = threadIdx.x;
    if (tid < H2DIM) zs[tid] = g_z2[bb * H2DIM + tid];
    __syncthreads();
    for (int j = tid; j < OUTD; j += 256) {
        float acc = b[j];
        #pragma unroll 8
        for (int k = 0; k < H2DIM; ++k) acc += zs[k] * w[(size_t)k * OUTD + j];
        out[(size_t)bb * OUTD + j] = acc;
    }
}

// -------------------------------- host -----------------------------------
extern "C" void kernel_launch(void* const* d_in, const int* in_sizes, int n_in,
                              void* d_out, int out_size) {
    const float* x   = (const float*)d_in[0];
    const float* adj = (const float*)d_in[1];
    const float* gw1 = (const float*)d_in[2];
    const float* gb1 = (const float*)d_in[3];
    const float* gw2 = (const float*)d_in[4];
    const float* gb2 = (const float*)d_in[5];
    const float* cw1 = (const float*)d_in[6];
    const float* cb1 = (const float*)d_in[7];
    const float* cw2 = (const float*)d_in[8];
    const float* cb2 = (const float*)d_in[9];
    const float* mw1 = (const float*)d_in[10];
    const float* mb1 = (const float*)d_in[11];
    const float* mw2 = (const float*)d_in[12];
    const float* mb2 = (const float*)d_in[13];
    const float* mw3 = (const float*)d_in[14];
    const float* mb3 = (const float*)d_in[15];
    float* out = (float*)d_out;

    float *h2p, *wp1p, *wp2p, *gbufp, *y1p, *y2p, *combp, *p1p;
    cudaGetSymbolAddress((void**)&h2p,   g_h2);
    cudaGetSymbolAddress((void**)&wp1p,  g_wp1);
    cudaGetSymbolAddress((void**)&wp2p,  g_wp2);
    cudaGetSymbolAddress((void**)&gbufp, g_gbuf);
    cudaGetSymbolAddress((void**)&y1p,   g_y1);
    cudaGetSymbolAddress((void**)&y2p,   g_y2);
    cudaGetSymbolAddress((void**)&combp, g_comb);
    cudaGetSymbolAddress((void**)&p1p,   g_p1);

    const int g2smem = (2 * ND + DDIM * DDIM + DDIM) * sizeof(float);  // 170240
    cudaFuncSetAttribute(gcn2_kernel, cudaFuncAttributeMaxDynamicSharedMemorySize, g2smem);

    // pack conv weights
    pack_conv_w<<<(ND * 384 + 255) / 256, 256>>>(cw1, wp1p, ND);
    pack_conv_w<<<(NC1 * 384 + 255) / 256, 256>>>(cw2, wp2p, NC1);

    // GCN layers
    gcn1_kernel<<<BT, 256>>>(x, adj, gw1, gb1);
    gcn2_kernel<<<BT, 256, g2smem>>>(adj, gw2, gb2);

    // conv1 as GEMM (1536 x 384 x 19200), split-K=2 for 2 CTAs/SM, + combine
    sgemm64<<<dim3(BT / 64, 384 / 64, CONV1_KS), 256>>>(h2p, ND, wp1p, 384, gbufp, 384,
                                                        ND / 16, ND / 16 / CONV1_KS,
                                                        GSTRIDE);
    conv_combine<<<(BT * 128 + 255) / 256, 256>>>(gbufp, cb1, y1p, CONV1_KS);

    // conv2 as GEMM (1536 x 384 x 128) + combine
    sgemm64<<<dim3(BT / 64, 384 / 64, 1), 256>>>(y1p, NC1, wp2p, 384, gbufp, 384,
                                                 NC1 / 16, NC1 / 16, 0);
    conv_combine<<<(BT * 128 + 255) / 256, 256>>>(gbufp, cb2, y2p, 1);

    // concat (with fused temporal pooling)
    gather_comb<<<(BDIM * MLPIN + 255) / 256, 256>>>();

    // MLP1: split-K GEMM (64 x 512 x 19328) -> fixed-order reduce
    sgemm64<<<dim3(1, H1DIM / 64, MLP1_KS), 256>>>(combp, MLPIN, mw1, H1DIM, p1p, H1DIM,
                                                   MLP1_STEPS, MLP1_SPS,
                                                   (size_t)64 * H1DIM);
    mlp1_reduce<<<(BDIM * H1DIM + 255) / 256, 256>>>(mb1);

    // MLP2 + MLP3
    mlp2_kernel<<<BDIM, 256>>>(mw2, mb2);
    mlp3_kernel<<<BDIM, 256>>>(mw3, mb3, out);
}

// round 6
// speedup vs baseline: 1.4926x; 1.4926x over previous
#include <cuda_runtime.h>

#define BDIM 64
#define TDIM 24
#define NNODE 300
#define FDIM 16
#define DDIM 64
#define BT (BDIM*TDIM)          // 1536
#define ND (NNODE*DDIM)         // 19200
#define NC1 128
#define NC2 128
#define MLPIN (ND + NC2)        // 19328
#define H1DIM 512
#define H2DIM 256
#define OUTD 3600               // N*H = 300*12
#define MLP1_STEPS (MLPIN/16)   // 1208
#define MLP1_KS 16
#define MLP1_SPS 76             // ceil(1208/16)
#define CONV1_KS 2              // split-K for conv1 GEMM
#define GSTRIDE ((size_t)BT*384)

#define MPAD 320                // padded node dim (rows)
#define KPAD 304                // padded node dim (K, 19*16)
#define NBTF (BT*FDIM)          // 24576
#define NBTD (BT*DDIM)          // 98304

// ---------------- device scratch (no allocations allowed) ----------------
__device__ float g_ap[(size_t)MPAD*KPAD];      // padded adj
__device__ float g_xt[(size_t)KPAD*NBTF];      // x transposed [n][(bt,f)]
__device__ float g_ax[(size_t)MPAD*NBTF];      // A@XT
__device__ float g_s2t[(size_t)KPAD*NBTD];     // S2 transposed [n][(bt,d)]
__device__ float g_h2t[(size_t)MPAD*NBTD];     // relu(A@S2T+b2) [m][(bt,d)]
__device__ float g_h2[(size_t)BT*ND];          // h2 [bt][(n,d)]
__device__ float g_wp1[(size_t)ND*384];
__device__ float g_wp2[(size_t)NC1*384];
__device__ float g_gbuf[(size_t)CONV1_KS*BT*384];
__device__ float g_y1[(size_t)BT*NC1];
__device__ float g_y2[(size_t)BT*NC2];
__device__ float g_comb[(size_t)BDIM*MLPIN];
__device__ float g_p1[(size_t)MLP1_KS*64*H1DIM];
__device__ float g_z1[BDIM*H1DIM];
__device__ float g_z2[BDIM*H2DIM];

// ---------------- pack conv weight: wp[i*384 + c*3+k] = w[c,i,k] ----------
__global__ void pack_conv_w(const float* __restrict__ w, float* __restrict__ wp, int cin) {
    int idx = blockIdx.x * 256 + threadIdx.x;
    int tot = cin * 384;
    if (idx >= tot) return;
    int i = idx / 384, j = idx % 384;
    int c = j / 3, k = j % 3;
    wp[idx] = w[((size_t)c * cin + i) * 3 + k];
}

// ---------------- build padded adjacency (320 x 304, zero pad) ------------
__global__ void build_ap(const float* __restrict__ adj) {
    int idx = blockIdx.x * 256 + threadIdx.x;
    if (idx >= MPAD * KPAD) return;
    int r = idx / KPAD, c = idx % KPAD;
    g_ap[idx] = (r < NNODE && c < NNODE) ? adj[r * NNODE + c] : 0.f;
}

// ---------------- XT[n][(bt,f)] = x[bt][n][f] -----------------------------
__global__ void transpose_x(const float* __restrict__ x) {
    int bt = blockIdx.x;
    const float4* src = (const float4*)(x + (size_t)bt * NNODE * FDIM);
    for (int i = threadIdx.x; i < NNODE * FDIM / 4; i += 256) {
        int n = i >> 2, f4 = i & 3;
        *(float4*)(g_xt + (size_t)n * NBTF + bt * FDIM + f4 * 4) = src[i];
    }
}

// ---- fused GCN weights stage: h1 = relu(AX@W1+b1); S2T = h1@W2 ----------
// block: one m (node), 32 bt values. AX row segment contiguous; output contiguous.
__global__ void __launch_bounds__(256) gcn_fuse(const float* __restrict__ w1,
                                                const float* __restrict__ b1,
                                                const float* __restrict__ w2) {
    __shared__ float axs[32 * 16];
    __shared__ float h1s[32 * 64];
    __shared__ float w1s[16 * 64];
    __shared__ float w2s[64 * 64];
    __shared__ float b1s[64];
    int m = blockIdx.x, bt0 = blockIdx.y * 32, tid = threadIdx.x;

    const float* axin = g_ax + (size_t)m * NBTF + bt0 * 16;
    for (int i = tid; i < 512; i += 256) axs[i] = axin[i];
    for (int i = tid; i < 1024; i += 256) w1s[i] = w1[i];
    for (int i = tid; i < 4096; i += 256) w2s[i] = w2[i];
    if (tid < 64) b1s[tid] = b1[tid];
    __syncthreads();

    // h1: 32 rows x 64 e; thread -> (r = tid>>3, e0 = (tid&7)*8)
    {
        int r = tid >> 3, e0 = (tid & 7) * 8;
        float acc[8];
        #pragma unroll
        for (int j = 0; j < 8; ++j) acc[j] = b1s[e0 + j];
        #pragma unroll
        for (int f = 0; f < 16; ++f) {
            float a = axs[r * 16 + f];
            #pragma unroll
            for (int j = 0; j < 8; ++j) acc[j] += a * w1s[f * 64 + e0 + j];
        }
        #pragma unroll
        for (int j = 0; j < 8; ++j) h1s[r * 64 + e0 + j] = fmaxf(acc[j], 0.f);
    }
    __syncthreads();

    // S2: 32 rows x 64 d; thread -> (r0 = (tid>>4)*2, d0 = (tid&15)*4)
    {
        int r0 = (tid >> 4) * 2, d0 = (tid & 15) * 4;
        float a00 = 0.f, a01 = 0.f, a02 = 0.f, a03 = 0.f;
        float a10 = 0.f, a11 = 0.f, a12 = 0.f, a13 = 0.f;
        #pragma unroll 8
        for (int e = 0; e < 64; ++e) {
            float4 bv = *(const float4*)&w2s[e * 64 + d0];
            float a0 = h1s[r0 * 64 + e];
            float a1 = h1s[r0 * 64 + 64 + e];
            a00 += a0 * bv.x; a01 += a0 * bv.y; a02 += a0 * bv.z; a03 += a0 * bv.w;
            a10 += a1 * bv.x; a11 += a1 * bv.y; a12 += a1 * bv.z; a13 += a1 * bv.w;
        }
        float* outp = g_s2t + (size_t)m * NBTD + (size_t)(bt0 + r0) * 64 + d0;
        *(float4*)outp = make_float4(a00, a01, a02, a03);
        *(float4*)(outp + 64) = make_float4(a10, a11, a12, a13);
    }
}

// ---------------- h2[bt][(n,d)] = H2T[n][(bt,d)] --------------------------
__global__ void transpose_h2() {
    int n = blockIdx.x, bt0 = blockIdx.y * 64;
    const float4* src = (const float4*)(g_h2t + (size_t)n * NBTD + (size_t)bt0 * 64);
    for (int i = threadIdx.x; i < 1024; i += 256) {
        int r = i >> 4, c = i & 15;
        *(float4*)(g_h2 + (size_t)(bt0 + r) * ND + n * 64 + c * 4) = src[i];
    }
}

// ------- generic 64x64 SGEMM, BK=16, double-buffered, split-K + epilogue --
// grid = (Mtiles, Ntiles, Ksplits). C row-major ldc. K = ktotal_steps*16.
// if bias != null: C = relu(C + bias[col & 63])
__global__ void __launch_bounds__(256) sgemm64(const float* __restrict__ A, int lda,
                                               const float* __restrict__ B, int ldb,
                                               float* __restrict__ C, int ldc,
                                               int ktotal_steps, int steps_per_split,
                                               size_t c_split_stride,
                                               const float* __restrict__ bias) {
    __shared__ float As[2][16][64];
    __shared__ float Bs[2][16][64];
    int tid = threadIdx.x;
    int r0 = blockIdx.x * 64, j0 = blockIdx.y * 64;
    int s0 = blockIdx.z * steps_per_split;
    int nst = ktotal_steps - s0;
    if (nst > steps_per_split) nst = steps_per_split;
    if (nst <= 0) return;
    C += (size_t)blockIdx.z * c_split_stride;

    int la_r = tid >> 2, la_k = (tid & 3) * 4;
    int lb_k = tid >> 4, lb_j = (tid & 15) * 4;
    const float* Ap = A + (size_t)(r0 + la_r) * lda + s0 * 16 + la_k;
    const float* Bp = B + ((size_t)s0 * 16 + lb_k) * ldb + j0 + lb_j;

    float4 a4 = *(const float4*)Ap;
    float4 b4 = *(const float4*)Bp;
    float acc[4][4] = {};
    int tc = tid & 15, tr = tid >> 4;
    int buf = 0;
    for (int s = 0; s < nst; ++s) {
        As[buf][la_k + 0][la_r] = a4.x;
        As[buf][la_k + 1][la_r] = a4.y;
        As[buf][la_k + 2][la_r] = a4.z;
        As[buf][la_k + 3][la_r] = a4.w;
        *(float4*)&Bs[buf][lb_k][lb_j] = b4;
        __syncthreads();
        if (s + 1 < nst) {
            a4 = *(const float4*)(Ap + (size_t)(s + 1) * 16);
            b4 = *(const float4*)(Bp + (size_t)(s + 1) * 16 * ldb);
        }
        #pragma unroll
        for (int kk = 0; kk < 16; ++kk) {
            float4 av = *(const float4*)&As[buf][kk][tr * 4];
            float4 bv = *(const float4*)&Bs[buf][kk][tc * 4];
            acc[0][0] += av.x * bv.x; acc[0][1] += av.x * bv.y; acc[0][2] += av.x * bv.z; acc[0][3] += av.x * bv.w;
            acc[1][0] += av.y * bv.x; acc[1][1] += av.y * bv.y; acc[1][2] += av.y * bv.z; acc[1][3] += av.y * bv.w;
            acc[2][0] += av.z * bv.x; acc[2][1] += av.z * bv.y; acc[2][2] += av.z * bv.z; acc[2][3] += av.z * bv.w;
            acc[3][0] += av.w * bv.x; acc[3][1] += av.w * bv.y; acc[3][2] += av.w * bv.z; acc[3][3] += av.w * bv.w;
        }
        buf ^= 1;
    }
    if (bias) {
        float b0 = bias[(j0 + tc * 4 + 0) & 63];
        float b1v = bias[(j0 + tc * 4 + 1) & 63];
        float b2v = bias[(j0 + tc * 4 + 2) & 63];
        float b3v = bias[(j0 + tc * 4 + 3) & 63];
        #pragma unroll
        for (int i = 0; i < 4; ++i) {
            acc[i][0] = fmaxf(acc[i][0] + b0, 0.f);
            acc[i][1] = fmaxf(acc[i][1] + b1v, 0.f);
            acc[i][2] = fmaxf(acc[i][2] + b2v, 0.f);
            acc[i][3] = fmaxf(acc[i][3] + b3v, 0.f);
        }
    }
    #pragma unroll
    for (int i = 0; i < 4; ++i) {
        *(float4*)&C[(size_t)(r0 + tr * 4 + i) * ldc + j0 + tc * 4] =
            make_float4(acc[i][0], acc[i][1], acc[i][2], acc[i][3]);
    }
}

// ------- temporal 3-tap combine over nsplit partial GEMM buffers ----------
__global__ void conv_combine(const float* __restrict__ G, const float* __restrict__ bias,
                             float* __restrict__ y, int nsplit) {
    int idx = blockIdx.x * 256 + threadIdx.x;
    if (idx >= BT * 128) return;
    int c = idx & 127;
    int bt = idx >> 7;
    int t = bt % TDIM;
    float v = bias[c];
    for (int s = 0; s < nsplit; ++s) {
        const float* Gs = G + (size_t)s * GSTRIDE;
        if (t > 0)        v += Gs[(size_t)(bt - 1) * 384 + c * 3 + 0];
        v += Gs[(size_t)bt * 384 + c * 3 + 1];
        if (t < TDIM - 1) v += Gs[(size_t)(bt + 1) * 384 + c * 3 + 2];
    }
    y[idx] = fmaxf(v, 0.f);
}

// ------- concat [last_spatial | mean_t(y2)]  (pool fused in) --------------
__global__ void gather_comb() {
    int idx = blockIdx.x * 256 + threadIdx.x;   // 64*19328
    if (idx >= BDIM * MLPIN) return;
    int b = idx / MLPIN, j = idx - b * MLPIN;
    if (j < ND) {
        g_comb[idx] = g_h2[((size_t)(b * TDIM + (TDIM - 1))) * ND + j];
    } else {
        int c = j - ND;
        float s = 0.f;
        #pragma unroll
        for (int t = 0; t < TDIM; ++t) s += g_y2[(size_t)(b * TDIM + t) * NC2 + c];
        g_comb[idx] = s * (1.f / TDIM);
    }
}

__global__ void mlp1_reduce(const float* __restrict__ b1) {
    int o = blockIdx.x * 256 + threadIdx.x;     // 64*512
    if (o >= BDIM * H1DIM) return;
    int j = o & (H1DIM - 1);
    float s = b1[j];
    #pragma unroll
    for (int ks = 0; ks < MLP1_KS; ++ks) s += g_p1[(size_t)ks * 64 * H1DIM + o];
    g_z1[o] = fmaxf(s, 0.f);
}

__global__ void __launch_bounds__(256) mlp2_kernel(const float* __restrict__ w,
                                                   const float* __restrict__ b) {
    __shared__ float zs[H1DIM];
    int bb = blockIdx.x, tid = threadIdx.x;
    zs[tid] = g_z1[bb * H1DIM + tid];
    zs[tid + 256] = g_z1[bb * H1DIM + tid + 256];
    __syncthreads();
    float acc = b[tid];
    #pragma unroll 8
    for (int k = 0; k < H1DIM; ++k) acc += zs[k] * w[(size_t)k * H2DIM + tid];
    g_z2[bb * H2DIM + tid] = fmaxf(acc, 0.f);
}

__global__ void __launch_bounds__(256) mlp3_kernel(const float* __restrict__ w,
                                                   const float* __restrict__ b,
                                                   float* __restrict__ out) {
    __shared__ float zs[H2DIM];
    int bb = blockIdx.x, tid = threadIdx.x;
    if (tid < H2DIM) zs[tid] = g_z2[bb * H2DIM + tid];
    __syncthreads();
    for (int j = tid; j < OUTD; j += 256) {
        float acc = b[j];
        #pragma unroll 8
        for (int k = 0; k < H2DIM; ++k) acc += zs[k] * w[(size_t)k * OUTD + j];
        out[(size_t)bb * OUTD + j] = acc;
    }
}

// -------------------------------- host -----------------------------------
extern "C" void kernel_launch(void* const* d_in, const int* in_sizes, int n_in,
                              void* d_out, int out_size) {
    const float* x   = (const float*)d_in[0];
    const float* adj = (const float*)d_in[1];
    const float* gw1 = (const float*)d_in[2];
    const float* gb1 = (const float*)d_in[3];
    const float* gw2 = (const float*)d_in[4];
    const float* gb2 = (const float*)d_in[5];
    const float* cw1 = (const float*)d_in[6];
    const float* cb1 = (const float*)d_in[7];
    const float* cw2 = (const float*)d_in[8];
    const float* cb2 = (const float*)d_in[9];
    const float* mw1 = (const float*)d_in[10];
    const float* mb1 = (const float*)d_in[11];
    const float* mw2 = (const float*)d_in[12];
    const float* mb2 = (const float*)d_in[13];
    const float* mw3 = (const float*)d_in[14];
    const float* mb3 = (const float*)d_in[15];
    float* out = (float*)d_out;

    float *app, *xtp, *axp, *s2tp, *h2tp, *h2p, *wp1p, *wp2p, *gbufp, *y1p, *y2p, *combp, *p1p;
    cudaGetSymbolAddress((void**)&app,   g_ap);
    cudaGetSymbolAddress((void**)&xtp,   g_xt);
    cudaGetSymbolAddress((void**)&axp,   g_ax);
    cudaGetSymbolAddress((void**)&s2tp,  g_s2t);
    cudaGetSymbolAddress((void**)&h2tp,  g_h2t);
    cudaGetSymbolAddress((void**)&h2p,   g_h2);
    cudaGetSymbolAddress((void**)&wp1p,  g_wp1);
    cudaGetSymbolAddress((void**)&wp2p,  g_wp2);
    cudaGetSymbolAddress((void**)&gbufp, g_gbuf);
    cudaGetSymbolAddress((void**)&y1p,   g_y1);
    cudaGetSymbolAddress((void**)&y2p,   g_y2);
    cudaGetSymbolAddress((void**)&combp, g_comb);
    cudaGetSymbolAddress((void**)&p1p,   g_p1);

    // zero the K-pad rows (rows 300..303) of XT and S2T
    cudaMemsetAsync(xtp + (size_t)NNODE * NBTF, 0, (size_t)(KPAD - NNODE) * NBTF * sizeof(float));
    cudaMemsetAsync(s2tp + (size_t)NNODE * NBTD, 0, (size_t)(KPAD - NNODE) * NBTD * sizeof(float));

    // pack weights / adjacency / inputs
    pack_conv_w<<<(ND * 384 + 255) / 256, 256>>>(cw1, wp1p, ND);
    pack_conv_w<<<(NC1 * 384 + 255) / 256, 256>>>(cw2, wp2p, NC1);
    build_ap<<<(MPAD * KPAD + 255) / 256, 256>>>(adj);
    transpose_x<<<BT, 256>>>(x);

    // GEMM1: AX = Ap @ XT   (320 x 24576 x 304)
    sgemm64<<<dim3(MPAD / 64, NBTF / 64, 1), 256>>>(app, KPAD, xtp, NBTF, axp, NBTF,
                                                    KPAD / 16, KPAD / 16, 0, nullptr);

    // fused: h1 = relu(AX@W1+b1); S2T = h1@W2
    gcn_fuse<<<dim3(NNODE, BT / 32), 256>>>(gw1, gb1, gw2);

    // GEMM2: H2T = relu(Ap @ S2T + b2)   (320 x 98304 x 304)
    sgemm64<<<dim3(MPAD / 64, NBTD / 64, 1), 256>>>(app, KPAD, s2tp, NBTD, h2tp, NBTD,
                                                    KPAD / 16, KPAD / 16, 0, gb2);

    // h2[bt][(n,d)] = H2T[n][(bt,d)]
    transpose_h2<<<dim3(NNODE, BT / 64), 256>>>();

    // conv1 as GEMM (1536 x 384 x 19200), split-K=2, + combine
    sgemm64<<<dim3(BT / 64, 384 / 64, CONV1_KS), 256>>>(h2p, ND, wp1p, 384, gbufp, 384,
                                                        ND / 16, ND / 16 / CONV1_KS,
                                                        GSTRIDE, nullptr);
    conv_combine<<<(BT * 128 + 255) / 256, 256>>>(gbufp, cb1, y1p, CONV1_KS);

    // conv2 as GEMM (1536 x 384 x 128) + combine
    sgemm64<<<dim3(BT / 64, 384 / 64, 1), 256>>>(y1p, NC1, wp2p, 384, gbufp, 384,
                                                 NC1 / 16, NC1 / 16, 0, nullptr);
    conv_combine<<<(BT * 128 + 255) / 256, 256>>>(gbufp, cb2, y2p, 1);

    // concat (with fused temporal pooling)
    gather_comb<<<(BDIM * MLPIN + 255) / 256, 256>>>();

    // MLP1: split-K GEMM (64 x 512 x 19328) -> fixed-order reduce
    sgemm64<<<dim3(1, H1DIM / 64, MLP1_KS), 256>>>(combp, MLPIN, mw1, H1DIM, p1p, H1DIM,
                                                   MLP1_STEPS, MLP1_SPS,
                                                   (size_t)64 * H1DIM, nullptr);
    mlp1_reduce<<<(BDIM * H1DIM + 255) / 256, 256>>>(mb1);

    // MLP2 + MLP3
    mlp2_kernel<<<BDIM, 256>>>(mw2, mb2);
    mlp3_kernel<<<BDIM, 256>>>(mw3, mb3, out);
}